// round 6
// baseline (speedup 1.0000x reference)
#include <cuda_runtime.h>

// MNIST_RNN: 2-layer LSTM (H=10), T=28, D=28, B=32768, + 10-way linear head.
// R4: split the time-independent x-projection (a [B*T,28]x[28,40] GEMM) into
// kernel A writing packed gate pairs (bias folded) into __device__ scratch
// xg[t][p][B]; kernel B does only the recurrent part (LDS/t drops 620->320)
// with a register double-buffer on the xg loads. Gate pairs accumulated with
// fma.rn.f32x2 throughout; weights read via volatile LDS (anti-LICM, see R3).

#define TT 28
#define DD 28
#define HH 10
#define GG 40   // 4*H gates
#define BMAX 32768

typedef unsigned long long u64;
typedef unsigned int u32;

// scratch: xg[t][p][b], p = gate-pair index 0..19 (packed f32x2)
__device__ u64 g_xg[(size_t)TT * 20 * BMAX];

__device__ __forceinline__ u32 smem_u32(const void *p) {
    u32 a;
    asm("{ .reg .u64 t; cvta.to.shared.u64 t, %1; cvt.u32.u64 %0, t; }"
        : "=r"(a) : "l"(p));
    return a;
}
__device__ __forceinline__ u64 pack2(float lo, float hi) {
    u64 r;
    asm("mov.b64 %0, {%1, %2};" : "=l"(r) : "f"(lo), "f"(hi));
    return r;
}
__device__ __forceinline__ void unpack2(u64 v, float &lo, float &hi) {
    asm("mov.b64 {%0, %1}, %2;" : "=f"(lo), "=f"(hi) : "l"(v));
}
__device__ __forceinline__ u64 ffma2(u64 a, u64 b, u64 c) {
    u64 d;
    asm("fma.rn.f32x2 %0, %1, %2, %3;" : "=l"(d) : "l"(a), "l"(b), "l"(c));
    return d;
}
// Non-hoistable shared loads (volatile asm = opaque to LICM/CSE).
__device__ __forceinline__ void lds_v2u64(u64 &w0, u64 &w1, u32 addr) {
    asm volatile("ld.shared.v2.u64 {%0, %1}, [%2];"
                 : "=l"(w0), "=l"(w1) : "r"(addr));
}
__device__ __forceinline__ u64 lds_u64(u32 addr) {
    u64 v;
    asm volatile("ld.shared.b64 %0, [%1];" : "=l"(v) : "r"(addr));
    return v;
}

// exp/rcp-based activations (MUFU.EX2 + MUFU.RCP): ~1e-6 abs error.
__device__ __forceinline__ float sigf(float x) {
    return __fdividef(1.0f, 1.0f + __expf(-x));
}
__device__ __forceinline__ float tanhf_(float x) {
    return 1.0f - 2.0f * __fdividef(1.0f, 1.0f + __expf(x + x));
}

// acc[2q],acc[2q+1] (gates 4q..4q+3) += xval * W[row][q]; row stride 160 B.
#define ACCROW(acc, Wbase, row, xval)                                   \
    {                                                                   \
        u64 _xx = pack2((xval), (xval));                                \
        _Pragma("unroll")                                               \
        for (int q = 0; q < 10; q++) {                                  \
            u64 _w0, _w1;                                               \
            lds_v2u64(_w0, _w1, (Wbase) + ((row) * 10 + q) * 16);       \
            acc[2 * q]     = ffma2(_xx, _w0, acc[2 * q]);               \
            acc[2 * q + 1] = ffma2(_xx, _w1, acc[2 * q + 1]);           \
        }                                                               \
    }

#define ACCROW4(acc, Wbase, base, v4)                                   \
    ACCROW(acc, Wbase, (base) + 0, (v4).x)                              \
    ACCROW(acc, Wbase, (base) + 1, (v4).y)                              \
    ACCROW(acc, Wbase, (base) + 2, (v4).z)                              \
    ACCROW(acc, Wbase, (base) + 3, (v4).w)

#define ACCH(acc, Wbase, hv)                                            \
    ACCROW(acc, Wbase, 0, hv[0]) ACCROW(acc, Wbase, 1, hv[1])           \
    ACCROW(acc, Wbase, 2, hv[2]) ACCROW(acc, Wbase, 3, hv[3])           \
    ACCROW(acc, Wbase, 4, hv[4]) ACCROW(acc, Wbase, 5, hv[5])           \
    ACCROW(acc, Wbase, 6, hv[6]) ACCROW(acc, Wbase, 7, hv[7])           \
    ACCROW(acc, Wbase, 8, hv[8]) ACCROW(acc, Wbase, 9, hv[9])

// LSTM pointwise update from packed gate pairs in acc.
// Hidden pair (2jj,2jj+1): i->acc[jj], f->acc[5+jj], g->acc[10+jj],
// o->acc[15+jj]; lane0/1 = hidden 2jj / 2jj+1.
#define CELL_UPDATE(acc, hv, cv)                                        \
    {                                                                   \
        _Pragma("unroll")                                               \
        for (int jj = 0; jj < 5; jj++) {                                \
            float i0, i1, f0, f1, g0, g1, o0, o1;                       \
            unpack2(acc[jj],      i0, i1);                              \
            unpack2(acc[5 + jj],  f0, f1);                              \
            unpack2(acc[10 + jj], g0, g1);                              \
            unpack2(acc[15 + jj], o0, o1);                              \
            float cn0 = sigf(f0) * cv[2 * jj]     + sigf(i0) * tanhf_(g0); \
            float cn1 = sigf(f1) * cv[2 * jj + 1] + sigf(i1) * tanhf_(g1); \
            cv[2 * jj]     = cn0;                                       \
            cv[2 * jj + 1] = cn1;                                       \
            hv[2 * jj]     = sigf(o0) * tanhf_(cn0);                    \
            hv[2 * jj + 1] = sigf(o1) * tanhf_(cn1);                    \
        }                                                               \
    }

// ---------------- kernel A: x projection ----------------
__global__ __launch_bounds__(128)
void xproj_kernel(const float *__restrict__ x,
                  const float *__restrict__ wih0,
                  const float *__restrict__ bih0,
                  const float *__restrict__ bhh0, int B) {
    __shared__ ulonglong2 sw[DD][10];
    __shared__ u64 sb[20];
    const int tid = threadIdx.x;
    for (int i = tid; i < DD * GG; i += 128) {
        int d = i / GG, g = i % GG;
        ((float *)sw)[i] = wih0[g * DD + d];
    }
    for (int i = tid; i < GG; i += 128)
        ((float *)sb)[i] = bih0[i] + bhh0[i];
    __syncthreads();

    const u32 sw_b = smem_u32(sw);
    const u32 sb_b = smem_u32(sb);

    const int idx = blockIdx.x * 128 + tid;
    const int t = idx / B;       // lanes keep consecutive b -> coalesced stores
    const int b = idx - t * B;
    if (t >= TT) return;

    const float4 *xr =
        reinterpret_cast<const float4 *>(x + ((size_t)b * TT + t) * DD);
    float4 xv0 = xr[0], xv1 = xr[1], xv2 = xr[2], xv3 = xr[3];
    float4 xv4 = xr[4], xv5 = xr[5], xv6 = xr[6];

    u64 a[20];
#pragma unroll
    for (int p = 0; p < 20; p++) a[p] = lds_u64(sb_b + p * 8);
    ACCROW4(a, sw_b, 0,  xv0)
    ACCROW4(a, sw_b, 4,  xv1)
    ACCROW4(a, sw_b, 8,  xv2)
    ACCROW4(a, sw_b, 12, xv3)
    ACCROW4(a, sw_b, 16, xv4)
    ACCROW4(a, sw_b, 20, xv5)
    ACCROW4(a, sw_b, 24, xv6)

    u64 *gp = g_xg + (size_t)t * 20 * B + b;
#pragma unroll
    for (int p = 0; p < 20; p++) gp[(size_t)p * B] = a[p];
}

// ---------------- kernel B: recurrent part ----------------
// One STEP: prefetch xg(t+1) into anxt, then consume acur for both layers.
#define STEP(acur, anxt, t)                                             \
    {                                                                   \
        const int _tn = ((t) < TT - 1) ? (t) + 1 : (t);                 \
        const u64 *_gp = g_xg + (size_t)_tn * 20 * B + b;               \
        _Pragma("unroll")                                               \
        for (int p = 0; p < 20; p++) anxt[p] = _gp[(size_t)p * B];      \
        ACCH(acur, w0h_b, h0)                                           \
        CELL_UPDATE(acur, h0, c0)                                       \
        _Pragma("unroll")                                               \
        for (int p = 0; p < 20; p++) acur[p] = lds_u64(sb1_b + p * 8);  \
        ACCH(acur, w1x_b, h0)                                           \
        ACCH(acur, w1h_b, h1)                                           \
        CELL_UPDATE(acur, h1, c1)                                       \
    }

__global__ __launch_bounds__(32)
void recur_kernel(const float *__restrict__ whh0,
                  const float *__restrict__ wih1, const float *__restrict__ whh1,
                  const float *__restrict__ bih1, const float *__restrict__ bhh1,
                  const float *__restrict__ wcls, const float *__restrict__ bcls,
                  float *__restrict__ out, int B) {
    __shared__ ulonglong2 sw0h[HH][10];
    __shared__ ulonglong2 sw1x[HH][10];
    __shared__ ulonglong2 sw1h[HH][10];
    __shared__ u64 sb1[20];
    __shared__ float swc[100], sbc[10];

    const int tid = threadIdx.x;
    for (int i = tid; i < HH * GG; i += 32) {
        int j = i / GG, g = i % GG;
        ((float *)sw0h)[i] = whh0[g * HH + j];
        ((float *)sw1x)[i] = wih1[g * HH + j];
        ((float *)sw1h)[i] = whh1[g * HH + j];
    }
    for (int i = tid; i < GG; i += 32)
        ((float *)sb1)[i] = bih1[i] + bhh1[i];
    for (int i = tid; i < 100; i += 32) swc[i] = wcls[i];
    for (int i = tid; i < 10; i += 32) sbc[i] = bcls[i];
    __syncthreads();

    const u32 w0h_b = smem_u32(sw0h);
    const u32 w1x_b = smem_u32(sw1x);
    const u32 w1h_b = smem_u32(sw1h);
    const u32 sb1_b = smem_u32(sb1);

    const int b = blockIdx.x * 32 + tid;
    if (b >= B) return;

    float h0[HH], c0[HH], h1[HH], c1[HH];
#pragma unroll
    for (int j = 0; j < HH; j++) { h0[j] = 0.f; c0[j] = 0.f; h1[j] = 0.f; c1[j] = 0.f; }

    u64 a0[20], a1[20];
    {   // preload t = 0
        const u64 *gp = g_xg + b;
#pragma unroll
        for (int p = 0; p < 20; p++) a0[p] = gp[(size_t)p * B];
    }

#pragma unroll 1
    for (int t = 0; t < TT; t += 2) {
        STEP(a0, a1, t)
        STEP(a1, a0, t + 1)
    }

    // classifier head
#pragma unroll
    for (int k = 0; k < 10; k++) {
        float s = sbc[k];
#pragma unroll
        for (int j = 0; j < HH; j++) s += h1[j] * swc[k * HH + j];
        out[(size_t)b * 10 + k] = s;
    }
}

extern "C" void kernel_launch(void *const *d_in, const int *in_sizes, int n_in,
                              void *d_out, int out_size) {
    const float *x    = (const float *)d_in[0];
    const float *wih0 = (const float *)d_in[1];
    const float *whh0 = (const float *)d_in[2];
    const float *bih0 = (const float *)d_in[3];
    const float *bhh0 = (const float *)d_in[4];
    const float *wih1 = (const float *)d_in[5];
    const float *whh1 = (const float *)d_in[6];
    const float *bih1 = (const float *)d_in[7];
    const float *bhh1 = (const float *)d_in[8];
    const float *wcls = (const float *)d_in[9];
    const float *bcls = (const float *)d_in[10];
    float *out = (float *)d_out;

    const int B = in_sizes[0] / (TT * DD);

    const long long rows = (long long)B * TT;
    const int gridA = (int)((rows + 127) / 128);
    xproj_kernel<<<gridA, 128>>>(x, wih0, bih0, bhh0, B);

    const int gridB = (B + 31) / 32;
    recur_kernel<<<gridB, 32>>>(whh0, wih1, whh1, bih1, bhh1,
                                wcls, bcls, out, B);
}

// round 8
// speedup vs baseline: 1.2489x; 1.2489x over previous
#include <cuda_runtime.h>
#include <cstdint>
#include <cstddef>

// MNIST_RNN: 2-layer LSTM (H=10), T=28, D=28, B=32768, + 10-way linear head.
// R7 = R6 with the uintptr_t compile fix. Fused single-pass structure,
// weights in __constant__ memory (the dedicated uniform-broadcast path; R3's
// profile showed smem crossbar charges LDS.128 by width even for broadcast,
// L1=71.6% bound). Weight reads are asm volatile ld.const (anti-LICM, R3).
// Pipeline: pack_kernel -> cudaMemcpyAsync D2D into __constant__ -> fused LSTM.

#define TT 28
#define DD 28
#define HH 10
#define GG 40   // 4*H gates

typedef unsigned long long u64;
typedef unsigned int u32;

// const blob layout (u64 units): gate-pair-major packed weights.
//   w0x [28 rows][10 q][2]  @ u64 0     (row = input dim d)
//   w0h [10][10][2]         @ u64 560
//   w1x [10][10][2]         @ u64 760
//   w1h [10][10][2]         @ u64 960
//   b0  [20]                @ u64 1160  (bih0+bhh0, packed pairs)
//   b1  [20]                @ u64 1180
#define C_W0X 0
#define C_W0H (560 * 8)
#define C_W1X (760 * 8)
#define C_W1H (960 * 8)
#define C_B0  (1160 * 8)
#define C_B1  (1180 * 8)
#define C_U64S 1200

__constant__ u64 c_blob[C_U64S];
__device__ u64 g_pack[C_U64S];

__device__ __forceinline__ u64 pack2(float lo, float hi) {
    u64 r;
    asm("mov.b64 %0, {%1, %2};" : "=l"(r) : "f"(lo), "f"(hi));
    return r;
}
__device__ __forceinline__ void unpack2(u64 v, float &lo, float &hi) {
    asm("mov.b64 {%0, %1}, %2;" : "=f"(lo), "=f"(hi) : "l"(v));
}
__device__ __forceinline__ u64 ffma2(u64 a, u64 b, u64 c) {
    u64 d;
    asm("fma.rn.f32x2 %0, %1, %2, %3;" : "=l"(d) : "l"(a), "l"(b), "l"(c));
    return d;
}
// const-space base address of c_blob
__device__ __forceinline__ u64 cblob_base() {
    u64 c;
    asm("cvta.to.const.u64 %0, %1;" : "=l"(c) : "l"((u64)(size_t)c_blob));
    return c;
}
// Non-hoistable constant loads (volatile = opaque to LICM/CSE; see R3).
__device__ __forceinline__ void ldc2(u64 &w0, u64 &w1, u64 addr) {
    asm volatile("ld.const.v2.u64 {%0, %1}, [%2];"
                 : "=l"(w0), "=l"(w1) : "l"(addr));
}

// exp/rcp-based activations (MUFU.EX2 + MUFU.RCP): ~1e-6 abs error.
__device__ __forceinline__ float sigf(float x) {
    return __fdividef(1.0f, 1.0f + __expf(-x));
}
__device__ __forceinline__ float tanhf_(float x) {
    return 1.0f - 2.0f * __fdividef(1.0f, 1.0f + __expf(x + x));
}

// a[2q],a[2q+1] (gates 4q..4q+3) += xval * W[row][q]; row stride 160 B.
#define ACCROW(a, cbase, rowoff, xval)                                  \
    {                                                                   \
        u64 _xx = pack2((xval), (xval));                                \
        _Pragma("unroll")                                               \
        for (int q = 0; q < 10; q++) {                                  \
            u64 _w0, _w1;                                               \
            ldc2(_w0, _w1, (cbase) + (u64)((rowoff) + q * 16));         \
            a[2 * q]     = ffma2(_xx, _w0, a[2 * q]);                   \
            a[2 * q + 1] = ffma2(_xx, _w1, a[2 * q + 1]);               \
        }                                                               \
    }

#define ACCROW4(a, cbase, base, v4)                                     \
    ACCROW(a, cbase, ((base) + 0) * 160, (v4).x)                        \
    ACCROW(a, cbase, ((base) + 1) * 160, (v4).y)                        \
    ACCROW(a, cbase, ((base) + 2) * 160, (v4).z)                        \
    ACCROW(a, cbase, ((base) + 3) * 160, (v4).w)

#define ACCH(a, cbase, hv)                                              \
    ACCROW(a, cbase, 0 * 160, hv[0]) ACCROW(a, cbase, 1 * 160, hv[1])   \
    ACCROW(a, cbase, 2 * 160, hv[2]) ACCROW(a, cbase, 3 * 160, hv[3])   \
    ACCROW(a, cbase, 4 * 160, hv[4]) ACCROW(a, cbase, 5 * 160, hv[5])   \
    ACCROW(a, cbase, 6 * 160, hv[6]) ACCROW(a, cbase, 7 * 160, hv[7])   \
    ACCROW(a, cbase, 8 * 160, hv[8]) ACCROW(a, cbase, 9 * 160, hv[9])

#define LOAD_BIAS(a, cbase)                                             \
    {                                                                   \
        _Pragma("unroll")                                               \
        for (int p = 0; p < 10; p++) {                                  \
            u64 _b0, _b1;                                               \
            ldc2(_b0, _b1, (cbase) + (u64)(p * 16));                    \
            a[2 * p] = _b0; a[2 * p + 1] = _b1;                         \
        }                                                               \
    }

// LSTM pointwise update. Hidden pair (2jj,2jj+1): i->a[jj], f->a[5+jj],
// g->a[10+jj], o->a[15+jj]; lane0/1 = hidden 2jj / 2jj+1.
#define CELL_UPDATE(a, hv, cv)                                          \
    {                                                                   \
        _Pragma("unroll")                                               \
        for (int jj = 0; jj < 5; jj++) {                                \
            float i0, i1, f0, f1, g0, g1, o0, o1;                       \
            unpack2(a[jj],      i0, i1);                                \
            unpack2(a[5 + jj],  f0, f1);                                \
            unpack2(a[10 + jj], g0, g1);                                \
            unpack2(a[15 + jj], o0, o1);                                \
            float cn0 = sigf(f0) * cv[2 * jj]     + sigf(i0) * tanhf_(g0); \
            float cn1 = sigf(f1) * cv[2 * jj + 1] + sigf(i1) * tanhf_(g1); \
            cv[2 * jj]     = cn0;                                       \
            cv[2 * jj + 1] = cn1;                                       \
            hv[2 * jj]     = sigf(o0) * tanhf_(cn0);                    \
            hv[2 * jj + 1] = sigf(o1) * tanhf_(cn1);                    \
        }                                                               \
    }

// ---- pack kernel: transpose weights into g_pack (float view) ----
__global__ __launch_bounds__(256)
void pack_kernel(const float *__restrict__ wih0, const float *__restrict__ whh0,
                 const float *__restrict__ bih0, const float *__restrict__ bhh0,
                 const float *__restrict__ wih1, const float *__restrict__ whh1,
                 const float *__restrict__ bih1, const float *__restrict__ bhh1) {
    float *f = (float *)g_pack;
    for (int i = threadIdx.x; i < DD * GG; i += 256) {   // w0x
        int d = i / GG, g = i % GG;
        f[i] = wih0[g * DD + d];
    }
    for (int i = threadIdx.x; i < HH * GG; i += 256) {   // w0h/w1x/w1h
        int j = i / GG, g = i % GG;
        f[1120 + i] = whh0[g * HH + j];
        f[1520 + i] = wih1[g * HH + j];
        f[1920 + i] = whh1[g * HH + j];
    }
    for (int i = threadIdx.x; i < GG; i += 256) {        // biases
        f[2320 + i] = bih0[i] + bhh0[i];
        f[2360 + i] = bih1[i] + bhh1[i];
    }
}

// ---- fused LSTM kernel ----
__global__ __launch_bounds__(32)
void mnist_rnn_kernel(const float *__restrict__ x,
                      const float *__restrict__ wcls,
                      const float *__restrict__ bcls,
                      float *__restrict__ out, int B) {
    const u64 cb = cblob_base();
    const u64 cb_w0x = cb + C_W0X;
    const u64 cb_w0h = cb + C_W0H;
    const u64 cb_w1x = cb + C_W1X;
    const u64 cb_w1h = cb + C_W1H;
    const u64 cb_b0  = cb + C_B0;
    const u64 cb_b1  = cb + C_B1;

    const int b = blockIdx.x * 32 + threadIdx.x;
    if (b >= B) return;

    const float *xb = x + (size_t)b * (TT * DD);

    float h0[HH], c0[HH], h1[HH], c1[HH];
#pragma unroll
    for (int j = 0; j < HH; j++) { h0[j] = 0.f; c0[j] = 0.f; h1[j] = 0.f; c1[j] = 0.f; }

#pragma unroll 1
    for (int t = 0; t < TT; t++) {
        // this timestep's x row: 7 x LDG.128 (MLP=7)
        const float4 *xr = reinterpret_cast<const float4 *>(xb + t * DD);
        float4 xv0 = xr[0], xv1 = xr[1], xv2 = xr[2], xv3 = xr[3];
        float4 xv4 = xr[4], xv5 = xr[5], xv6 = xr[6];

        u64 a[20];

        // ---- layer 0 ----
        LOAD_BIAS(a, cb_b0)
        ACCROW4(a, cb_w0x, 0,  xv0)
        ACCROW4(a, cb_w0x, 4,  xv1)
        ACCROW4(a, cb_w0x, 8,  xv2)
        ACCROW4(a, cb_w0x, 12, xv3)
        ACCROW4(a, cb_w0x, 16, xv4)
        ACCROW4(a, cb_w0x, 20, xv5)
        ACCROW4(a, cb_w0x, 24, xv6)
        ACCH(a, cb_w0h, h0)
        CELL_UPDATE(a, h0, c0)

        // ---- layer 1 ----
        LOAD_BIAS(a, cb_b1)
        ACCH(a, cb_w1x, h0)
        ACCH(a, cb_w1h, h1)
        CELL_UPDATE(a, h1, c1)
    }

    // classifier head (one-shot; tiny broadcast reads straight from gmem)
#pragma unroll
    for (int k = 0; k < 10; k++) {
        float s = __ldg(bcls + k);
#pragma unroll
        for (int j = 0; j < HH; j++) s += h1[j] * __ldg(wcls + k * HH + j);
        out[(size_t)b * 10 + k] = s;
    }
}

extern "C" void kernel_launch(void *const *d_in, const int *in_sizes, int n_in,
                              void *d_out, int out_size) {
    const float *x    = (const float *)d_in[0];
    const float *wih0 = (const float *)d_in[1];
    const float *whh0 = (const float *)d_in[2];
    const float *bih0 = (const float *)d_in[3];
    const float *bhh0 = (const float *)d_in[4];
    const float *wih1 = (const float *)d_in[5];
    const float *whh1 = (const float *)d_in[6];
    const float *bih1 = (const float *)d_in[7];
    const float *bhh1 = (const float *)d_in[8];
    const float *wcls = (const float *)d_in[9];
    const float *bcls = (const float *)d_in[10];
    float *out = (float *)d_out;

    const int B = in_sizes[0] / (TT * DD);

    pack_kernel<<<1, 256>>>(wih0, whh0, bih0, bhh0, wih1, whh1, bih1, bhh1);

    void *dst = nullptr, *src = nullptr;
    cudaGetSymbolAddress(&dst, c_blob);
    cudaGetSymbolAddress(&src, g_pack);
    cudaMemcpyAsync(dst, src, C_U64S * sizeof(u64), cudaMemcpyDeviceToDevice, 0);

    const int grid = (B + 31) / 32;
    mnist_rnn_kernel<<<grid, 32>>>(x, wcls, bcls, out, B);
}

// round 9
// speedup vs baseline: 2.9265x; 2.3433x over previous
#include <cuda_runtime.h>
#include <cstdint>
#include <cstddef>

// MNIST_RNN: 2-layer LSTM (H=10), T=28, D=28, B=32768, + 10-way linear head.
// R8: back to the R3 fused smem design (const-mem was half-rate, R7: 586us),
// but each thread now processes TWO batch elements (b, b+B/2), so every
// weight LDS feeds 4 FFMA2s. Measured R3: broadcast LDS.128 ~1.65cyc ->
// LDS/SM demand halves below fma-pipe demand; binder flips to fma (~70us
// ideal). Weight reads stay asm-volatile LDS (anti-LICM spill fix, R3).
// x rows software-pipelined in groups of 4 dims to cap register pressure.

#define TT 28
#define DD 28
#define HH 10
#define GG 40   // 4*H gates

typedef unsigned long long u64;
typedef unsigned int u32;

__device__ __forceinline__ u32 smem_u32(const void *p) {
    u32 a;
    asm("{ .reg .u64 t; cvta.to.shared.u64 t, %1; cvt.u32.u64 %0, t; }"
        : "=r"(a) : "l"(p));
    return a;
}
__device__ __forceinline__ u64 pack2(float lo, float hi) {
    u64 r;
    asm("mov.b64 %0, {%1, %2};" : "=l"(r) : "f"(lo), "f"(hi));
    return r;
}
__device__ __forceinline__ void unpack2(u64 v, float &lo, float &hi) {
    asm("mov.b64 {%0, %1}, %2;" : "=f"(lo), "=f"(hi) : "l"(v));
}
__device__ __forceinline__ u64 ffma2(u64 a, u64 b, u64 c) {
    u64 d;
    asm("fma.rn.f32x2 %0, %1, %2, %3;" : "=l"(d) : "l"(a), "l"(b), "l"(c));
    return d;
}
// Non-hoistable shared loads (volatile = opaque to LICM/CSE; see R3).
__device__ __forceinline__ void lds_v2u64(u64 &w0, u64 &w1, u32 addr) {
    asm volatile("ld.shared.v2.u64 {%0, %1}, [%2];"
                 : "=l"(w0), "=l"(w1) : "r"(addr));
}

// exp/rcp-based activations (MUFU.EX2 + MUFU.RCP): ~1e-6 abs error.
__device__ __forceinline__ float sigf(float x) {
    return __fdividef(1.0f, 1.0f + __expf(-x));
}
__device__ __forceinline__ float tanhf_(float x) {
    return 1.0f - 2.0f * __fdividef(1.0f, 1.0f + __expf(x + x));
}

// One weight load feeds both elements: 1 LDS.128 -> 4 FFMA2.
#define ACCROW2(Wbase, row, xa, xb)                                     \
    {                                                                   \
        u64 _va = pack2((xa), (xa));                                    \
        u64 _vb = pack2((xb), (xb));                                    \
        _Pragma("unroll")                                               \
        for (int q = 0; q < 10; q++) {                                  \
            u64 _w0, _w1;                                               \
            lds_v2u64(_w0, _w1, (Wbase) + ((row) * 10 + q) * 16);       \
            aA[2 * q]     = ffma2(_va, _w0, aA[2 * q]);                 \
            aA[2 * q + 1] = ffma2(_va, _w1, aA[2 * q + 1]);             \
            aB[2 * q]     = ffma2(_vb, _w0, aB[2 * q]);                 \
            aB[2 * q + 1] = ffma2(_vb, _w1, aB[2 * q + 1]);             \
        }                                                               \
    }

#define ACCROW2x4(Wbase, base, va4, vb4)                                \
    ACCROW2(Wbase, (base) + 0, (va4).x, (vb4).x)                        \
    ACCROW2(Wbase, (base) + 1, (va4).y, (vb4).y)                        \
    ACCROW2(Wbase, (base) + 2, (va4).z, (vb4).z)                        \
    ACCROW2(Wbase, (base) + 3, (va4).w, (vb4).w)

#define ACCH2(Wbase, hA, hB)                                            \
    ACCROW2(Wbase, 0, hA[0], hB[0]) ACCROW2(Wbase, 1, hA[1], hB[1])     \
    ACCROW2(Wbase, 2, hA[2], hB[2]) ACCROW2(Wbase, 3, hA[3], hB[3])     \
    ACCROW2(Wbase, 4, hA[4], hB[4]) ACCROW2(Wbase, 5, hA[5], hB[5])     \
    ACCROW2(Wbase, 6, hA[6], hB[6]) ACCROW2(Wbase, 7, hA[7], hB[7])     \
    ACCROW2(Wbase, 8, hA[8], hB[8]) ACCROW2(Wbase, 9, hA[9], hB[9])

#define LOAD_BIAS2(Bbase)                                               \
    {                                                                   \
        _Pragma("unroll")                                               \
        for (int p = 0; p < 10; p++) {                                  \
            u64 _b0, _b1;                                               \
            lds_v2u64(_b0, _b1, (Bbase) + p * 16);                      \
            aA[2 * p] = _b0; aA[2 * p + 1] = _b1;                       \
            aB[2 * p] = _b0; aB[2 * p + 1] = _b1;                       \
        }                                                               \
    }

// LSTM pointwise update from packed gate pairs in acc.
// Hidden pair (2jj,2jj+1): i->acc[jj], f->acc[5+jj], g->acc[10+jj],
// o->acc[15+jj]; lane0/1 = hidden 2jj / 2jj+1.
#define CELL_UPDATE(acc, hv, cv)                                        \
    {                                                                   \
        _Pragma("unroll")                                               \
        for (int jj = 0; jj < 5; jj++) {                                \
            float i0, i1, f0, f1, g0, g1, o0, o1;                       \
            unpack2(acc[jj],      i0, i1);                              \
            unpack2(acc[5 + jj],  f0, f1);                              \
            unpack2(acc[10 + jj], g0, g1);                              \
            unpack2(acc[15 + jj], o0, o1);                              \
            float cn0 = sigf(f0) * cv[2 * jj]     + sigf(i0) * tanhf_(g0); \
            float cn1 = sigf(f1) * cv[2 * jj + 1] + sigf(i1) * tanhf_(g1); \
            cv[2 * jj]     = cn0;                                       \
            cv[2 * jj + 1] = cn1;                                       \
            hv[2 * jj]     = sigf(o0) * tanhf_(cn0);                    \
            hv[2 * jj + 1] = sigf(o1) * tanhf_(cn1);                    \
        }                                                               \
    }

__global__ __launch_bounds__(32)
void mnist_rnn_kernel(const float *__restrict__ x,
                      const float *__restrict__ wih0, const float *__restrict__ whh0,
                      const float *__restrict__ bih0, const float *__restrict__ bhh0,
                      const float *__restrict__ wih1, const float *__restrict__ whh1,
                      const float *__restrict__ bih1, const float *__restrict__ bhh1,
                      const float *__restrict__ wcls, const float *__restrict__ bcls,
                      float *__restrict__ out, int B) {
    // Packed weights: float view index [input*40 + gate] == gate-major pairs.
    __shared__ ulonglong2 sw0x[DD][10];   // w_ih0
    __shared__ ulonglong2 sw0h[HH][10];   // w_hh0
    __shared__ ulonglong2 sw1x[HH][10];   // w_ih1
    __shared__ ulonglong2 sw1h[HH][10];   // w_hh1
    __shared__ u64 sb0[20], sb1[20];      // combined biases, packed pairs
    __shared__ float swc[100], sbc[10];

    const int tid = threadIdx.x;
    for (int i = tid; i < DD * GG; i += 32) {
        int d = i / GG, g = i % GG;
        ((float *)sw0x)[i] = wih0[g * DD + d];
    }
    for (int i = tid; i < HH * GG; i += 32) {
        int j = i / GG, g = i % GG;
        ((float *)sw0h)[i] = whh0[g * HH + j];
        ((float *)sw1x)[i] = wih1[g * HH + j];
        ((float *)sw1h)[i] = whh1[g * HH + j];
    }
    for (int i = tid; i < GG; i += 32) {
        ((float *)sb0)[i] = bih0[i] + bhh0[i];
        ((float *)sb1)[i] = bih1[i] + bhh1[i];
    }
    for (int i = tid; i < 100; i += 32) swc[i] = wcls[i];
    for (int i = tid; i < 10; i += 32) sbc[i] = bcls[i];
    __syncthreads();

    const u32 w0x_b = smem_u32(sw0x);
    const u32 w0h_b = smem_u32(sw0h);
    const u32 w1x_b = smem_u32(sw1x);
    const u32 w1h_b = smem_u32(sw1h);
    const u32 sb0_b = smem_u32(sb0);
    const u32 sb1_b = smem_u32(sb1);

    const int Bh = B >> 1;            // two elements per thread: b and b+B/2
    const int bA = blockIdx.x * 32 + tid;
    if (bA >= Bh) return;
    const int bB = bA + Bh;

    const float *xbA = x + (size_t)bA * (TT * DD);
    const float *xbB = x + (size_t)bB * (TT * DD);

    float h0A[HH], c0A[HH], h1A[HH], c1A[HH];
    float h0B[HH], c0B[HH], h1B[HH], c1B[HH];
#pragma unroll
    for (int j = 0; j < HH; j++) {
        h0A[j] = 0.f; c0A[j] = 0.f; h1A[j] = 0.f; c1A[j] = 0.f;
        h0B[j] = 0.f; c0B[j] = 0.f; h1B[j] = 0.f; c1B[j] = 0.f;
    }

#pragma unroll 1
    for (int t = 0; t < TT; t++) {
        const float4 *xrA = reinterpret_cast<const float4 *>(xbA + t * DD);
        const float4 *xrB = reinterpret_cast<const float4 *>(xbB + t * DD);

        u64 aA[20], aB[20];

        // ---- layer 0: x projection, software-pipelined x groups ----
        LOAD_BIAS2(sb0_b)
        float4 vac = xrA[0], vbc = xrB[0];   // current group
        float4 van, vbn;                      // next group
        van = xrA[1]; vbn = xrB[1];
        ACCROW2x4(w0x_b, 0, vac, vbc)
        vac = van; vbc = vbn; van = xrA[2]; vbn = xrB[2];
        ACCROW2x4(w0x_b, 4, vac, vbc)
        vac = van; vbc = vbn; van = xrA[3]; vbn = xrB[3];
        ACCROW2x4(w0x_b, 8, vac, vbc)
        vac = van; vbc = vbn; van = xrA[4]; vbn = xrB[4];
        ACCROW2x4(w0x_b, 12, vac, vbc)
        vac = van; vbc = vbn; van = xrA[5]; vbn = xrB[5];
        ACCROW2x4(w0x_b, 16, vac, vbc)
        vac = van; vbc = vbn; van = xrA[6]; vbn = xrB[6];
        ACCROW2x4(w0x_b, 20, vac, vbc)
        vac = van; vbc = vbn;
        ACCROW2x4(w0x_b, 24, vac, vbc)

        // recurrent part of layer 0
        ACCH2(w0h_b, h0A, h0B)
        CELL_UPDATE(aA, h0A, c0A)
        CELL_UPDATE(aB, h0B, c0B)

        // ---- layer 1 ----
        LOAD_BIAS2(sb1_b)
        ACCH2(w1x_b, h0A, h0B)
        ACCH2(w1h_b, h1A, h1B)
        CELL_UPDATE(aA, h1A, c1A)
        CELL_UPDATE(aB, h1B, c1B)
    }

    // classifier head for both elements
#pragma unroll
    for (int k = 0; k < 10; k++) {
        float sA = sbc[k], sB = sbc[k];
#pragma unroll
        for (int j = 0; j < HH; j++) {
            float w = swc[k * HH + j];
            sA += h1A[j] * w;
            sB += h1B[j] * w;
        }
        out[(size_t)bA * 10 + k] = sA;
        out[(size_t)bB * 10 + k] = sB;
    }
}

extern "C" void kernel_launch(void *const *d_in, const int *in_sizes, int n_in,
                              void *d_out, int out_size) {
    const float *x    = (const float *)d_in[0];
    const float *wih0 = (const float *)d_in[1];
    const float *whh0 = (const float *)d_in[2];
    const float *bih0 = (const float *)d_in[3];
    const float *bhh0 = (const float *)d_in[4];
    const float *wih1 = (const float *)d_in[5];
    const float *whh1 = (const float *)d_in[6];
    const float *bih1 = (const float *)d_in[7];
    const float *bhh1 = (const float *)d_in[8];
    const float *wcls = (const float *)d_in[9];
    const float *bcls = (const float *)d_in[10];
    float *out = (float *)d_out;

    const int B = in_sizes[0] / (TT * DD);
    const int Bh = B >> 1;
    const int grid = (Bh + 31) / 32;
    mnist_rnn_kernel<<<grid, 32>>>(x, wih0, whh0, bih0, bhh0,
                                   wih1, whh1, bih1, bhh1,
                                   wcls, bcls, out, B);
}

// round 10
// speedup vs baseline: 4.4246x; 1.5119x over previous
#include <cuda_runtime.h>
#include <cstdint>
#include <cstddef>

// MNIST_RNN: 2-layer LSTM (H=10), T=28, D=28, B=32768, + 10-way linear head.
// R9: 2 batch elements per THREAD-PAIR, gates split across the pair.
//  - lane role 0 (even) accumulates i,f gates (local pairs 0..9) for elems A,B
//  - lane role 1 (odd)  accumulates g,o gates for the same two elems
// Each weight LDS.128 feeds 4 FFMA2s (2-elem amortization, R8) while total
// warps stay at 1024 (1.73/SMSP, R3-level latency hiding). Per-layer the pair
// exchanges 10 acc u64s + h via shfl.xor 1; role selection via SEL (no
// divergence). Weight reads stay asm-volatile LDS (anti-LICM, R3).

#define TT 28
#define DD 28
#define HH 10

typedef unsigned long long u64;
typedef unsigned int u32;

__device__ __forceinline__ u32 smem_u32(const void *p) {
    u32 a;
    asm("{ .reg .u64 t; cvta.to.shared.u64 t, %1; cvt.u32.u64 %0, t; }"
        : "=r"(a) : "l"(p));
    return a;
}
__device__ __forceinline__ u64 pack2(float lo, float hi) {
    u64 r;
    asm("mov.b64 %0, {%1, %2};" : "=l"(r) : "f"(lo), "f"(hi));
    return r;
}
__device__ __forceinline__ void unpack2(u64 v, float &lo, float &hi) {
    asm("mov.b64 {%0, %1}, %2;" : "=f"(lo), "=f"(hi) : "l"(v));
}
__device__ __forceinline__ u64 ffma2(u64 a, u64 b, u64 c) {
    u64 d;
    asm("fma.rn.f32x2 %0, %1, %2, %3;" : "=l"(d) : "l"(a), "l"(b), "l"(c));
    return d;
}
// Non-hoistable shared loads (volatile = opaque to LICM/CSE; see R3).
__device__ __forceinline__ void lds_v2u64(u64 &w0, u64 &w1, u32 addr) {
    asm volatile("ld.shared.v2.u64 {%0, %1}, [%2];"
                 : "=l"(w0), "=l"(w1) : "r"(addr));
}
__device__ __forceinline__ float shflx1_f(float v) {
    return __shfl_xor_sync(0xffffffffu, v, 1);
}
__device__ __forceinline__ u64 shflx1_u64(u64 v) {
    u32 lo, hi;
    asm("mov.b64 {%0, %1}, %2;" : "=r"(lo), "=r"(hi) : "l"(v));
    lo = __shfl_xor_sync(0xffffffffu, lo, 1);
    hi = __shfl_xor_sync(0xffffffffu, hi, 1);
    u64 r;
    asm("mov.b64 %0, {%1, %2};" : "=l"(r) : "r"(lo), "r"(hi));
    return r;
}

// exp/rcp-based activations (MUFU.EX2 + MUFU.RCP): ~1e-6 abs error.
__device__ __forceinline__ float sigf(float x) {
    return __fdividef(1.0f, 1.0f + __expf(-x));
}
__device__ __forceinline__ float tanhf_(float x) {
    return 1.0f - 2.0f * __fdividef(1.0f, 1.0f + __expf(x + x));
}

// smem u64 blob offsets (u64 units). Per-role regions; row = 10 u64 = 80 B.
//  w0x [2][28][10] @0   w0h [2][10][10] @560   w1x @760   w1h @960
//  b0  [2][10]     @1160  b1 [2][10]    @1180
#define U_W0X 0
#define U_W0H 560
#define U_W1X 760
#define U_W1H 960
#define U_B0  1160
#define U_B1  1180
#define U_TOT 1200

// Accumulate one input row into this role's 10 local gate pairs (both elems).
#define ACCROW2S(Wt, row, xa, xb)                                       \
    {                                                                   \
        u64 _va = pack2((xa), (xa));                                    \
        u64 _vb = pack2((xb), (xb));                                    \
        _Pragma("unroll")                                               \
        for (int qq = 0; qq < 5; qq++) {                                \
            u64 _w0, _w1;                                               \
            lds_v2u64(_w0, _w1, (Wt) + ((row) * 5 + qq) * 16);          \
            aA[2 * qq]     = ffma2(_va, _w0, aA[2 * qq]);               \
            aA[2 * qq + 1] = ffma2(_va, _w1, aA[2 * qq + 1]);           \
            aB[2 * qq]     = ffma2(_vb, _w0, aB[2 * qq]);               \
            aB[2 * qq + 1] = ffma2(_vb, _w1, aB[2 * qq + 1]);           \
        }                                                               \
    }

#define ACCROW2S4(Wt, base, va4, vb4)                                   \
    ACCROW2S(Wt, (base) + 0, (va4).x, (vb4).x)                          \
    ACCROW2S(Wt, (base) + 1, (va4).y, (vb4).y)                          \
    ACCROW2S(Wt, (base) + 2, (va4).z, (vb4).z)                          \
    ACCROW2S(Wt, (base) + 3, (va4).w, (vb4).w)

#define ACCH2S(Wt, hA, hB)                                              \
    ACCROW2S(Wt, 0, hA[0], hB[0]) ACCROW2S(Wt, 1, hA[1], hB[1])         \
    ACCROW2S(Wt, 2, hA[2], hB[2]) ACCROW2S(Wt, 3, hA[3], hB[3])         \
    ACCROW2S(Wt, 4, hA[4], hB[4]) ACCROW2S(Wt, 5, hA[5], hB[5])         \
    ACCROW2S(Wt, 6, hA[6], hB[6]) ACCROW2S(Wt, 7, hA[7], hB[7])         \
    ACCROW2S(Wt, 8, hA[8], hB[8]) ACCROW2S(Wt, 9, hA[9], hB[9])

#define LOAD_BIAS2S(Bt)                                                 \
    {                                                                   \
        _Pragma("unroll")                                               \
        for (int qq = 0; qq < 5; qq++) {                                \
            u64 _b0, _b1;                                               \
            lds_v2u64(_b0, _b1, (Bt) + qq * 16);                        \
            aA[2 * qq] = _b0; aA[2 * qq + 1] = _b1;                     \
            aB[2 * qq] = _b0; aB[2 * qq + 1] = _b1;                     \
        }                                                               \
    }

// Exchange accs with partner lane, update MY element's cell state (cv),
// write role-resolved hA/hB arrays for the next accumulation.
// role0: my elem = A, own accs = i,f; partner supplies g,o of A.
// role1: my elem = B, own accs = g,o; partner supplies i,f of B.
#define EXCH_UPDATE(hA, hB, cv)                                         \
    {                                                                   \
        u64 rcv[10];                                                    \
        _Pragma("unroll")                                               \
        for (int k = 0; k < 10; k++) {                                  \
            u64 snd = role ? aA[k] : aB[k];                             \
            rcv[k] = shflx1_u64(snd);                                   \
        }                                                               \
        _Pragma("unroll")                                               \
        for (int jj = 0; jj < 5; jj++) {                                \
            u64 Pi = role ? rcv[jj]     : aA[jj];                       \
            u64 Pf = role ? rcv[5 + jj] : aA[5 + jj];                   \
            u64 Pg = role ? aB[jj]      : rcv[jj];                      \
            u64 Po = role ? aB[5 + jj]  : rcv[5 + jj];                  \
            float i0, i1, f0, f1, g0, g1, o0, o1;                       \
            unpack2(Pi, i0, i1); unpack2(Pf, f0, f1);                   \
            unpack2(Pg, g0, g1); unpack2(Po, o0, o1);                   \
            float cn0 = sigf(f0) * cv[2 * jj]     + sigf(i0) * tanhf_(g0); \
            float cn1 = sigf(f1) * cv[2 * jj + 1] + sigf(i1) * tanhf_(g1); \
            cv[2 * jj] = cn0; cv[2 * jj + 1] = cn1;                     \
            float hm0 = sigf(o0) * tanhf_(cn0);                         \
            float hm1 = sigf(o1) * tanhf_(cn1);                         \
            float ho0 = shflx1_f(hm0);                                  \
            float ho1 = shflx1_f(hm1);                                  \
            hA[2 * jj]     = role ? ho0 : hm0;                          \
            hB[2 * jj]     = role ? hm0 : ho0;                          \
            hA[2 * jj + 1] = role ? ho1 : hm1;                          \
            hB[2 * jj + 1] = role ? hm1 : ho1;                          \
        }                                                               \
    }

__global__ __launch_bounds__(32)
void mnist_rnn_kernel(const float *__restrict__ x,
                      const float *__restrict__ wih0, const float *__restrict__ whh0,
                      const float *__restrict__ bih0, const float *__restrict__ bhh0,
                      const float *__restrict__ wih1, const float *__restrict__ whh1,
                      const float *__restrict__ bih1, const float *__restrict__ bhh1,
                      const float *__restrict__ wcls, const float *__restrict__ bcls,
                      float *__restrict__ out, int B) {
    __shared__ u64 blob[U_TOT];
    __shared__ float swc[100], sbc[10];

    const int tid = threadIdx.x;
    {
        float *f = (float *)blob;
        for (int i = tid; i < 1120; i += 32) {              // w0x
            int r = i / 560, rem = i % 560;
            int d = rem / 20, gg = rem % 20;
            f[i] = wih0[(20 * r + gg) * DD + d];
        }
        for (int i = tid; i < 400; i += 32) {               // w0h/w1x/w1h
            int r = i / 200, rem = i % 200;
            int j = rem / 20, gg = rem % 20;
            f[1120 + i] = whh0[(20 * r + gg) * HH + j];
            f[1520 + i] = wih1[(20 * r + gg) * HH + j];
            f[1920 + i] = whh1[(20 * r + gg) * HH + j];
        }
        for (int i = tid; i < 40; i += 32) {                // biases
            int r = i / 20, gg = i % 20;
            f[2320 + i] = bih0[20 * r + gg] + bhh0[20 * r + gg];
            f[2360 + i] = bih1[20 * r + gg] + bhh1[20 * r + gg];
        }
        for (int i = tid; i < 100; i += 32) swc[i] = wcls[i];
        for (int i = tid; i < 10; i += 32) sbc[i] = bcls[i];
    }
    __syncthreads();

    const u32 sbase = smem_u32(blob);
    const int role = tid & 1;
    const u32 w0x_t = sbase + U_W0X * 8 + role * (28 * 80);
    const u32 w0h_t = sbase + U_W0H * 8 + role * (10 * 80);
    const u32 w1x_t = sbase + U_W1X * 8 + role * (10 * 80);
    const u32 w1h_t = sbase + U_W1H * 8 + role * (10 * 80);
    const u32 sb0_t = sbase + U_B0 * 8 + role * 80;
    const u32 sb1_t = sbase + U_B1 * 8 + role * 80;

    const int Bh = B >> 1;
    const int pairIdx = blockIdx.x * 16 + (tid >> 1);
    if (pairIdx >= Bh) return;
    const int bA = pairIdx, bB = pairIdx + Bh;

    const float *xbA = x + (size_t)bA * (TT * DD);
    const float *xbB = x + (size_t)bB * (TT * DD);

    float h0A[HH], h0B[HH], h1A[HH], h1B[HH];   // role-resolved hidden states
    float c0m[HH], c1m[HH];                      // MY element's cell states
#pragma unroll
    for (int j = 0; j < HH; j++) {
        h0A[j] = 0.f; h0B[j] = 0.f; h1A[j] = 0.f; h1B[j] = 0.f;
        c0m[j] = 0.f; c1m[j] = 0.f;
    }

#pragma unroll 1
    for (int t = 0; t < TT; t++) {
        const float4 *xrA = reinterpret_cast<const float4 *>(xbA + t * DD);
        const float4 *xrB = reinterpret_cast<const float4 *>(xbB + t * DD);

        u64 aA[10], aB[10];

        // ---- layer 0: x projection (software-pipelined x groups) ----
        LOAD_BIAS2S(sb0_t)
        float4 vac = xrA[0], vbc = xrB[0];
        float4 van = xrA[1], vbn = xrB[1];
        ACCROW2S4(w0x_t, 0, vac, vbc)
        vac = van; vbc = vbn; van = xrA[2]; vbn = xrB[2];
        ACCROW2S4(w0x_t, 4, vac, vbc)
        vac = van; vbc = vbn; van = xrA[3]; vbn = xrB[3];
        ACCROW2S4(w0x_t, 8, vac, vbc)
        vac = van; vbc = vbn; van = xrA[4]; vbn = xrB[4];
        ACCROW2S4(w0x_t, 12, vac, vbc)
        vac = van; vbc = vbn; van = xrA[5]; vbn = xrB[5];
        ACCROW2S4(w0x_t, 16, vac, vbc)
        vac = van; vbc = vbn; van = xrA[6]; vbn = xrB[6];
        ACCROW2S4(w0x_t, 20, vac, vbc)
        vac = van; vbc = vbn;
        ACCROW2S4(w0x_t, 24, vac, vbc)

        // recurrent part of layer 0, then exchange + pointwise update
        ACCH2S(w0h_t, h0A, h0B)
        EXCH_UPDATE(h0A, h0B, c0m)

        // ---- layer 1 ----
        LOAD_BIAS2S(sb1_t)
        ACCH2S(w1x_t, h0A, h0B)
        ACCH2S(w1h_t, h1A, h1B)
        EXCH_UPDATE(h1A, h1B, c1m)
    }

    // classifier head: each thread writes its own element
    const int bm = role ? bB : bA;
#pragma unroll
    for (int k = 0; k < 10; k++) {
        float s = sbc[k];
#pragma unroll
        for (int j = 0; j < HH; j++) {
            float hm = role ? h1B[j] : h1A[j];
            s += hm * swc[k * HH + j];
        }
        out[(size_t)bm * 10 + k] = s;
    }
}

extern "C" void kernel_launch(void *const *d_in, const int *in_sizes, int n_in,
                              void *d_out, int out_size) {
    const float *x    = (const float *)d_in[0];
    const float *wih0 = (const float *)d_in[1];
    const float *whh0 = (const float *)d_in[2];
    const float *bih0 = (const float *)d_in[3];
    const float *bhh0 = (const float *)d_in[4];
    const float *wih1 = (const float *)d_in[5];
    const float *whh1 = (const float *)d_in[6];
    const float *bih1 = (const float *)d_in[7];
    const float *bhh1 = (const float *)d_in[8];
    const float *wcls = (const float *)d_in[9];
    const float *bcls = (const float *)d_in[10];
    float *out = (float *)d_out;

    const int B = in_sizes[0] / (TT * DD);
    const int Bh = B >> 1;
    const int grid = (Bh + 15) / 16;
    mnist_rnn_kernel<<<grid, 32>>>(x, wih0, whh0, bih0, bhh0,
                                   wih1, whh1, bih1, bhh1,
                                   wcls, bcls, out, B);
}